// round 5
// baseline (speedup 1.0000x reference)
#include <cuda_runtime.h>
#include <cuda_fp16.h>

#define NN   50000
#define NE   800000
#define NB   4
#define IND  64
#define HIDD 64
#define OUTD 32
#define NROWS (NN * NB)          // 200000

typedef unsigned long long u64;

// ---------------- scratch (static device globals) ----------------
__device__ __align__(16) __half g_z1[(size_t)NN * NB * HIDD];  // fp16 (h@W1)*snorm, node-major [q=n*4+b][64]
__device__ __align__(16) __half g_z2[(size_t)NN * NB * OUTD];  // fp16 snorm*(relu(agg*dn+b1)@W2)
__device__ float g_snorm[NN];
__device__ float g_dnorm[NN];
__device__ int   g_odeg[NN];
__device__ int   g_ideg[NN];
__device__ int   g_incl[NN];
__device__ int   g_bsum[128];
__device__ int   g_boff[128];
__device__ int   g_coff[NN];
__device__ int   g_cur [NN];
__device__ int   g_esrc[NE];

// ---------------- f32x2 packed-FMA helpers (Blackwell FFMA2) ----------------
__device__ __forceinline__ u64 pack2(float x, float y) {
    u64 r; asm("mov.b64 %0, {%1,%2};" : "=l"(r) : "f"(x), "f"(y)); return r;
}
__device__ __forceinline__ void ffma2(u64& d, u64 a, u64 b) {
    asm("fma.rn.f32x2 %0, %1, %2, %0;" : "+l"(d) : "l"(a), "l"(b));
}
__device__ __forceinline__ float2 unpack2(u64 v) {
    float2 f; asm("mov.b64 {%0,%1}, %2;" : "=f"(f.x), "=f"(f.y) : "l"(v)); return f;
}

// ---------------- small prep kernels ----------------

__global__ void k_zero_deg() {
    int i = blockIdx.x * blockDim.x + threadIdx.x;
    if (i < NN) { g_odeg[i] = 0; g_ideg[i] = 0; }
}

__global__ void k_deg(const int* __restrict__ src, const int* __restrict__ dst) {
    int i = blockIdx.x * blockDim.x + threadIdx.x;
    int stride = gridDim.x * blockDim.x;
    for (int e = i; e < NE; e += stride) {
        atomicAdd(&g_odeg[__ldg(src + e)], 1);
        atomicAdd(&g_ideg[__ldg(dst + e)], 1);
    }
}

#define SCAN_BLK 512
#define N_SCAN_BLKS ((NN + SCAN_BLK - 1) / SCAN_BLK)   // 98

// warp-shuffle inclusive scan over 512 elems / block
__global__ void k_scan1() {
    __shared__ int ws[16];
    int t = threadIdx.x, g = blockIdx.x * SCAN_BLK + t;
    int v = (g < NN) ? g_ideg[g] : 0;
    int x = v;
    #pragma unroll
    for (int o = 1; o < 32; o <<= 1) {
        int y = __shfl_up_sync(0xffffffffu, x, o);
        if ((t & 31) >= o) x += y;
    }
    if ((t & 31) == 31) ws[t >> 5] = x;
    __syncthreads();
    if (t < 32) {
        int s = (t < 16) ? ws[t] : 0;
        #pragma unroll
        for (int o = 1; o < 16; o <<= 1) {
            int y = __shfl_up_sync(0xffffffffu, s, o);
            if (t >= o) s += y;
        }
        if (t < 16) ws[t] = s;
    }
    __syncthreads();
    int base = (t >> 5) ? ws[(t >> 5) - 1] : 0;
    int incl = x + base;
    if (g < NN) g_incl[g] = incl;
    if (t == SCAN_BLK - 1) g_bsum[blockIdx.x] = incl;
}

__global__ void k_scan2() {   // 1 block, 128 threads (N_SCAN_BLKS = 98)
    __shared__ int ws[4];
    int t = threadIdx.x;
    int v = (t < N_SCAN_BLKS) ? g_bsum[t] : 0;
    int x = v;
    #pragma unroll
    for (int o = 1; o < 32; o <<= 1) {
        int y = __shfl_up_sync(0xffffffffu, x, o);
        if ((t & 31) >= o) x += y;
    }
    if ((t & 31) == 31) ws[t >> 5] = x;
    __syncthreads();
    if (t < 32) {
        int s = (t < 4) ? ws[t] : 0;
        #pragma unroll
        for (int o = 1; o < 4; o <<= 1) {
            int y = __shfl_up_sync(0xffffffffu, s, o);
            if (t >= o) s += y;
        }
        if (t < 4) ws[t] = s;
    }
    __syncthreads();
    int base = (t >> 5) ? ws[(t >> 5) - 1] : 0;
    if (t < N_SCAN_BLKS) g_boff[t] = x + base - v;   // exclusive
}

// scan finalize + norms (k_norm fused here)
__global__ void k_scan3() {
    int g = blockIdx.x * blockDim.x + threadIdx.x;
    if (g < NN) {
        int id = g_ideg[g];
        int ex = g_incl[g] - id + g_boff[g / SCAN_BLK];
        g_coff[g] = ex;
        g_cur[g]  = ex;
        g_snorm[g] = rsqrtf((float)max(g_odeg[g], 1));
        g_dnorm[g] = rsqrtf((float)max(id, 1));
    }
}

__global__ void k_fill(const int* __restrict__ src, const int* __restrict__ dst) {
    int i = blockIdx.x * blockDim.x + threadIdx.x;
    int stride = gridDim.x * blockDim.x;
    for (int e = i; e < NE; e += stride) {
        int d = __ldg(dst + e);
        int pos = atomicAdd(&g_cur[d], 1);
        g_esrc[pos] = __ldg(src + e);
    }
}

// ---------------- GEMM 1: z1[q=n*4+b] = half( snorm[n] * (h[r=b*NN+n] @ W1) ) ----------------
__global__ void __launch_bounds__(256) k_gemm1(const float* __restrict__ h,
                                               const float* __restrict__ W1) {
    __shared__ float sA[IND][128];   // transposed + XOR-swizzled
    __shared__ float sB[IND * HIDD];
    int tid = threadIdx.x;
    int lane = tid & 31;
    int cgrp = tid >> 5;
    int c0 = cgrp * 8;
    int row0 = blockIdx.x * 128;

    #pragma unroll
    for (int i = tid; i < IND * HIDD; i += 256) sB[i] = __ldg(W1 + i);
    #pragma unroll
    for (int it = 0; it < 8; it++) {
        int idx = tid + it * 256;
        int r_l = idx >> 4;
        int kq  = idx & 15;
        int row = row0 + r_l;
        float4 v = make_float4(0.f, 0.f, 0.f, 0.f);
        if (row < NROWS) v = __ldg((const float4*)(h + (size_t)row * IND + kq * 4));
        int col = r_l ^ kq;
        sA[kq * 4 + 0][col] = v.x;
        sA[kq * 4 + 1][col] = v.y;
        sA[kq * 4 + 2][col] = v.z;
        sA[kq * 4 + 3][col] = v.w;
    }
    __syncthreads();

    u64 acc[4][4];
    #pragma unroll
    for (int r = 0; r < 4; r++)
        #pragma unroll
        for (int c = 0; c < 4; c++) acc[r][c] = 0ull;

    #pragma unroll 4
    for (int k = 0; k < IND; k++) {
        int s = (k >> 2) & 15;
        u64 ap[4];
        #pragma unroll
        for (int r = 0; r < 4; r++) {
            float a = sA[k][(lane + 32 * r) ^ s];
            ap[r] = pack2(a, a);
        }
        ulonglong2 b01 = *(const ulonglong2*)&sB[k * HIDD + c0];
        ulonglong2 b23 = *(const ulonglong2*)&sB[k * HIDD + c0 + 4];
        u64 bp[4] = {b01.x, b01.y, b23.x, b23.y};
        #pragma unroll
        for (int r = 0; r < 4; r++)
            #pragma unroll
            for (int c = 0; c < 4; c++) ffma2(acc[r][c], ap[r], bp[c]);
    }

    #pragma unroll
    for (int r = 0; r < 4; r++) {
        int row = row0 + lane + 32 * r;
        if (row >= NROWS) continue;
        int b = row / NN, n = row - b * NN;
        float sc = g_snorm[n];
        int q = n * NB + b;
        float2 p0 = unpack2(acc[r][0]), p1 = unpack2(acc[r][1]);
        float2 p2 = unpack2(acc[r][2]), p3 = unpack2(acc[r][3]);
        __half2 h0 = __floats2half2_rn(sc * p0.x, sc * p0.y);
        __half2 h1 = __floats2half2_rn(sc * p1.x, sc * p1.y);
        __half2 h2 = __floats2half2_rn(sc * p2.x, sc * p2.y);
        __half2 h3 = __floats2half2_rn(sc * p3.x, sc * p3.y);
        uint4 st;
        st.x = *(unsigned*)&h0; st.y = *(unsigned*)&h1;
        st.z = *(unsigned*)&h2; st.w = *(unsigned*)&h3;
        *(uint4*)(g_z1 + (size_t)q * HIDD + c0) = st;   // 16B aligned
    }
}

// ---------------- FUSED gather-1 + layer-2 GEMM ----------------
// warp per node (grid-stride). Phase A: accumulate agg row [4b x 64k] fp32,
// lane owns elements [lane*8 .. lane*8+7]  (b = lane>>3, k = (lane&7)*8 + t).
// Phase B: y[t] = relu(a[t]*dnorm + b1[k_own]); in-warp GEMM vs W2 (smem):
// lane computes out[b][f0..f0+3], f0=(lane&7)*4; y broadcast via shfl.
// Store z2 fp16 = snorm * out.
__global__ void __launch_bounds__(256) k_agg_gemm2(const float* __restrict__ W2,
                                                   const float* __restrict__ b1) {
    __shared__ float sW2[HIDD * OUTD];   // 8 KB, [k][f]
    __shared__ float sb1[HIDD];
    int tid = threadIdx.x;
    int lane = tid & 31;
    #pragma unroll
    for (int i = tid; i < HIDD * OUTD; i += 256) sW2[i] = __ldg(W2 + i);
    if (tid < HIDD) sb1[tid] = __ldg(b1 + tid);
    __syncthreads();

    int gwarp = (blockIdx.x * blockDim.x + tid) >> 5;
    int nwarps = (gridDim.x * blockDim.x) >> 5;
    int f0 = (lane & 7) * 4;
    int kbase = (lane & 7) * 8;

    for (int n = gwarp; n < NN; n += nwarps) {
        int beg = g_coff[n];
        int deg = g_ideg[n];

        // Phase A: gather-accumulate
        float2 a[4];
        #pragma unroll
        for (int j = 0; j < 4; j++) a[j] = make_float2(0.f, 0.f);
        int i = 0;
        for (; i + 1 < deg; i += 2) {
            int s0 = __ldg(g_esrc + beg + i);
            int s1 = __ldg(g_esrc + beg + i + 1);
            uint4 v0 = __ldg((const uint4*)(g_z1 + (size_t)s0 * (NB * HIDD)) + lane);
            uint4 v1 = __ldg((const uint4*)(g_z1 + (size_t)s1 * (NB * HIDD)) + lane);
            const unsigned* w0 = &v0.x;
            const unsigned* w1 = &v1.x;
            #pragma unroll
            for (int j = 0; j < 4; j++) {
                float2 f0v = __half22float2(*(const __half2*)&w0[j]);
                float2 f1v = __half22float2(*(const __half2*)&w1[j]);
                a[j].x += f0v.x + f1v.x;
                a[j].y += f0v.y + f1v.y;
            }
        }
        if (i < deg) {
            int s0 = __ldg(g_esrc + beg + i);
            uint4 v0 = __ldg((const uint4*)(g_z1 + (size_t)s0 * (NB * HIDD)) + lane);
            const unsigned* w0 = &v0.x;
            #pragma unroll
            for (int j = 0; j < 4; j++) {
                float2 f0v = __half22float2(*(const __half2*)&w0[j]);
                a[j].x += f0v.x;
                a[j].y += f0v.y;
            }
        }

        // Phase B: relu + in-warp GEMM
        float dn = g_dnorm[n];
        float y[8];
        #pragma unroll
        for (int j = 0; j < 4; j++) {
            y[2 * j]     = fmaxf(a[j].x * dn + sb1[kbase + 2 * j],     0.f);
            y[2 * j + 1] = fmaxf(a[j].y * dn + sb1[kbase + 2 * j + 1], 0.f);
        }

        u64 acc0 = 0ull, acc1 = 0ull;
        #pragma unroll
        for (int k = 0; k < HIDD; k++) {
            float yv = __shfl_sync(0xffffffffu, y[k & 7], (lane & 24) + (k >> 3));
            u64 yp = pack2(yv, yv);
            ulonglong2 w = *(const ulonglong2*)&sW2[k * OUTD + f0];
            ffma2(acc0, yp, w.x);
            ffma2(acc1, yp, w.y);
        }

        float sc = g_snorm[n];
        float2 p0 = unpack2(acc0), p1 = unpack2(acc1);
        __half2 h0 = __floats2half2_rn(sc * p0.x, sc * p0.y);
        __half2 h1 = __floats2half2_rn(sc * p1.x, sc * p1.y);
        uint2 st;
        st.x = *(unsigned*)&h0; st.y = *(unsigned*)&h1;
        // q = n*4 + b, b = lane>>3; halves offset q*32 + f0
        *(uint2*)(g_z2 + ((size_t)n * NB + (lane >> 3)) * OUTD + f0) = st;
    }
}

// ---------------- gather layer 2 + fused epilogue -> out[b][n][f] ----------------
__global__ void __launch_bounds__(256) k_agg2(const float* __restrict__ b2,
                                              float* __restrict__ out) {
    int lane = threadIdx.x & 31;
    int n = blockIdx.x * 8 + (threadIdx.x >> 5);
    if (n >= NN) return;
    int beg = g_coff[n];
    int deg = g_ideg[n];
    float2 a0 = make_float2(0.f, 0.f), a1 = a0;

    int i = 0;
    for (; i + 1 < deg; i += 2) {
        int s0 = __ldg(g_esrc + beg + i);
        int s1 = __ldg(g_esrc + beg + i + 1);
        uint2 v0 = __ldg((const uint2*)(g_z2 + (size_t)s0 * (NB * OUTD)) + lane);
        uint2 v1 = __ldg((const uint2*)(g_z2 + (size_t)s1 * (NB * OUTD)) + lane);
        float2 f;
        f = __half22float2(*(const __half2*)&v0.x); a0.x += f.x; a0.y += f.y;
        f = __half22float2(*(const __half2*)&v0.y); a1.x += f.x; a1.y += f.y;
        f = __half22float2(*(const __half2*)&v1.x); a0.x += f.x; a0.y += f.y;
        f = __half22float2(*(const __half2*)&v1.y); a1.x += f.x; a1.y += f.y;
    }
    if (i < deg) {
        int s0 = __ldg(g_esrc + beg + i);
        uint2 v0 = __ldg((const uint2*)(g_z2 + (size_t)s0 * (NB * OUTD)) + lane);
        float2 f;
        f = __half22float2(*(const __half2*)&v0.x); a0.x += f.x; a0.y += f.y;
        f = __half22float2(*(const __half2*)&v0.y); a1.x += f.x; a1.y += f.y;
    }

    float dn = g_dnorm[n];
    int b = lane >> 3, fq = lane & 7;
    float4 bb = __ldg((const float4*)(b2 + fq * 4));
    float4 o = make_float4(a0.x * dn + bb.x, a0.y * dn + bb.y,
                           a1.x * dn + bb.z, a1.y * dn + bb.w);
    *(float4*)(out + ((size_t)b * NN + n) * OUTD + fq * 4) = o;
}

// ---------------- launch ----------------

extern "C" void kernel_launch(void* const* d_in, const int* in_sizes, int n_in,
                              void* d_out, int out_size) {
    const float* h  = (const float*)d_in[0];
    const float* W1 = (const float*)d_in[1];
    const float* b1 = (const float*)d_in[2];
    const float* W2 = (const float*)d_in[3];
    const float* b2 = (const float*)d_in[4];
    const int* src  = (const int*)d_in[5];
    const int* dst  = (const int*)d_in[6];
    float* out = (float*)d_out;

    k_zero_deg<<<(NN + 255) / 256, 256>>>();
    k_deg<<<2048, 256>>>(src, dst);
    k_scan1<<<N_SCAN_BLKS, SCAN_BLK>>>();
    k_scan2<<<1, 128>>>();
    k_scan3<<<(NN + 255) / 256, 256>>>();
    k_fill<<<2048, 256>>>(src, dst);
    k_gemm1<<<(NROWS + 127) / 128, 256>>>(h, W1);
    k_agg_gemm2<<<782, 256>>>(W2, b1);
    k_agg2<<<(NN + 7) / 8, 256>>>(b2, out);
}

// round 6
// speedup vs baseline: 1.1528x; 1.1528x over previous
#include <cuda_runtime.h>
#include <cuda_fp16.h>

#define NN   50000
#define NE   800000
#define NB   4
#define IND  64
#define HIDD 64
#define OUTD 32
#define NROWS (NN * NB)          // 200000

typedef unsigned long long u64;

// ---------------- scratch (static device globals) ----------------
__device__ __align__(16) __half g_z1[(size_t)NN * NB * HIDD];  // fp16 (h@W1)*snorm, node-major [q=n*4+b][64]
__device__ __align__(16) float  g_agg1[(size_t)NN * NB * HIDD];
__device__ __align__(16) __half g_z2[(size_t)NN * NB * OUTD];  // fp16 snorm*(relu(agg*dn+b1)@W2)
__device__ float g_snorm[NN];
__device__ float g_dnorm[NN];
__device__ int   g_odeg[NN];
__device__ int   g_ideg[NN];
__device__ int   g_incl[NN];
__device__ int   g_bsum[128];
__device__ int   g_boff[128];
__device__ int   g_coff[NN];
__device__ int   g_cur [NN];
__device__ int   g_esrc[NE];

// ---------------- f32x2 packed-FMA helpers (Blackwell FFMA2) ----------------
__device__ __forceinline__ u64 pack2(float x, float y) {
    u64 r; asm("mov.b64 %0, {%1,%2};" : "=l"(r) : "f"(x), "f"(y)); return r;
}
__device__ __forceinline__ void ffma2(u64& d, u64 a, u64 b) {
    asm("fma.rn.f32x2 %0, %1, %2, %0;" : "+l"(d) : "l"(a), "l"(b));
}
__device__ __forceinline__ float2 unpack2(u64 v) {
    float2 f; asm("mov.b64 {%0,%1}, %2;" : "=f"(f.x), "=f"(f.y) : "l"(v)); return f;
}

// ---------------- small prep kernels ----------------

__global__ void k_zero_deg() {
    int i = blockIdx.x * blockDim.x + threadIdx.x;
    if (i < NN) { g_odeg[i] = 0; g_ideg[i] = 0; }
}

__global__ void k_deg(const int* __restrict__ src, const int* __restrict__ dst) {
    int i = blockIdx.x * blockDim.x + threadIdx.x;
    int stride = gridDim.x * blockDim.x;
    for (int e = i; e < NE; e += stride) {
        atomicAdd(&g_odeg[__ldg(src + e)], 1);
        atomicAdd(&g_ideg[__ldg(dst + e)], 1);
    }
}

#define SCAN_BLK 512
#define N_SCAN_BLKS ((NN + SCAN_BLK - 1) / SCAN_BLK)   // 98

// warp-shuffle inclusive scan over 512 elems / block
__global__ void k_scan1() {
    __shared__ int ws[16];
    int t = threadIdx.x, g = blockIdx.x * SCAN_BLK + t;
    int v = (g < NN) ? g_ideg[g] : 0;
    int x = v;
    #pragma unroll
    for (int o = 1; o < 32; o <<= 1) {
        int y = __shfl_up_sync(0xffffffffu, x, o);
        if ((t & 31) >= o) x += y;
    }
    if ((t & 31) == 31) ws[t >> 5] = x;
    __syncthreads();
    if (t < 32) {
        int s = (t < 16) ? ws[t] : 0;
        #pragma unroll
        for (int o = 1; o < 16; o <<= 1) {
            int y = __shfl_up_sync(0xffffffffu, s, o);
            if (t >= o) s += y;
        }
        if (t < 16) ws[t] = s;
    }
    __syncthreads();
    int base = (t >> 5) ? ws[(t >> 5) - 1] : 0;
    int incl = x + base;
    if (g < NN) g_incl[g] = incl;
    if (t == SCAN_BLK - 1) g_bsum[blockIdx.x] = incl;
}

__global__ void k_scan2() {   // 1 block, 128 threads (N_SCAN_BLKS = 98)
    __shared__ int ws[4];
    int t = threadIdx.x;
    int v = (t < N_SCAN_BLKS) ? g_bsum[t] : 0;
    int x = v;
    #pragma unroll
    for (int o = 1; o < 32; o <<= 1) {
        int y = __shfl_up_sync(0xffffffffu, x, o);
        if ((t & 31) >= o) x += y;
    }
    if ((t & 31) == 31) ws[t >> 5] = x;
    __syncthreads();
    if (t < 32) {
        int s = (t < 4) ? ws[t] : 0;
        #pragma unroll
        for (int o = 1; o < 4; o <<= 1) {
            int y = __shfl_up_sync(0xffffffffu, s, o);
            if (t >= o) s += y;
        }
        if (t < 4) ws[t] = s;
    }
    __syncthreads();
    int base = (t >> 5) ? ws[(t >> 5) - 1] : 0;
    if (t < N_SCAN_BLKS) g_boff[t] = x + base - v;   // exclusive
}

// scan finalize + norms (k_norm fused here)
__global__ void k_scan3() {
    int g = blockIdx.x * blockDim.x + threadIdx.x;
    if (g < NN) {
        int id = g_ideg[g];
        int ex = g_incl[g] - id + g_boff[g / SCAN_BLK];
        g_coff[g] = ex;
        g_cur[g]  = ex;
        g_snorm[g] = rsqrtf((float)max(g_odeg[g], 1));
        g_dnorm[g] = rsqrtf((float)max(id, 1));
    }
}

__global__ void k_fill(const int* __restrict__ src, const int* __restrict__ dst) {
    int i = blockIdx.x * blockDim.x + threadIdx.x;
    int stride = gridDim.x * blockDim.x;
    for (int e = i; e < NE; e += stride) {
        int d = __ldg(dst + e);
        int pos = atomicAdd(&g_cur[d], 1);
        g_esrc[pos] = __ldg(src + e);
    }
}

// ---------------- GEMM 1: z1[q=n*4+b] = half( snorm[n] * (h[r=b*NN+n] @ W1) ) ----------------
__global__ void __launch_bounds__(256) k_gemm1(const float* __restrict__ h,
                                               const float* __restrict__ W1) {
    __shared__ float sA[IND][128];   // transposed + XOR-swizzled
    __shared__ float sB[IND * HIDD];
    int tid = threadIdx.x;
    int lane = tid & 31;
    int cgrp = tid >> 5;
    int c0 = cgrp * 8;
    int row0 = blockIdx.x * 128;

    #pragma unroll
    for (int i = tid; i < IND * HIDD; i += 256) sB[i] = __ldg(W1 + i);
    #pragma unroll
    for (int it = 0; it < 8; it++) {
        int idx = tid + it * 256;
        int r_l = idx >> 4;
        int kq  = idx & 15;
        int row = row0 + r_l;
        float4 v = make_float4(0.f, 0.f, 0.f, 0.f);
        if (row < NROWS) v = __ldg((const float4*)(h + (size_t)row * IND + kq * 4));
        int col = r_l ^ kq;
        sA[kq * 4 + 0][col] = v.x;
        sA[kq * 4 + 1][col] = v.y;
        sA[kq * 4 + 2][col] = v.z;
        sA[kq * 4 + 3][col] = v.w;
    }
    __syncthreads();

    u64 acc[4][4];
    #pragma unroll
    for (int r = 0; r < 4; r++)
        #pragma unroll
        for (int c = 0; c < 4; c++) acc[r][c] = 0ull;

    #pragma unroll 4
    for (int k = 0; k < IND; k++) {
        int s = (k >> 2) & 15;
        u64 ap[4];
        #pragma unroll
        for (int r = 0; r < 4; r++) {
            float a = sA[k][(lane + 32 * r) ^ s];
            ap[r] = pack2(a, a);
        }
        ulonglong2 b01 = *(const ulonglong2*)&sB[k * HIDD + c0];
        ulonglong2 b23 = *(const ulonglong2*)&sB[k * HIDD + c0 + 4];
        u64 bp[4] = {b01.x, b01.y, b23.x, b23.y};
        #pragma unroll
        for (int r = 0; r < 4; r++)
            #pragma unroll
            for (int c = 0; c < 4; c++) ffma2(acc[r][c], ap[r], bp[c]);
    }

    #pragma unroll
    for (int r = 0; r < 4; r++) {
        int row = row0 + lane + 32 * r;
        if (row >= NROWS) continue;
        int b = row / NN, n = row - b * NN;
        float sc = g_snorm[n];
        int q = n * NB + b;
        float2 p0 = unpack2(acc[r][0]), p1 = unpack2(acc[r][1]);
        float2 p2 = unpack2(acc[r][2]), p3 = unpack2(acc[r][3]);
        __half2 h0 = __floats2half2_rn(sc * p0.x, sc * p0.y);
        __half2 h1 = __floats2half2_rn(sc * p1.x, sc * p1.y);
        __half2 h2 = __floats2half2_rn(sc * p2.x, sc * p2.y);
        __half2 h3 = __floats2half2_rn(sc * p3.x, sc * p3.y);
        uint4 st;
        st.x = *(unsigned*)&h0; st.y = *(unsigned*)&h1;
        st.z = *(unsigned*)&h2; st.w = *(unsigned*)&h3;
        *(uint4*)(g_z1 + (size_t)q * HIDD + c0) = st;   // 16B aligned
    }
}

// ---------------- gather layer 1: agg1[n] = sum z1[src]  (fp16 in, fp32 acc/out) ----------------
// warp per node; node row = 256 halves = 512B -> per lane one 16B load.
// 4-deep batched loads for MLP.
__global__ void __launch_bounds__(256) k_agg1() {
    int lane = threadIdx.x & 31;
    int n = blockIdx.x * 8 + (threadIdx.x >> 5);
    if (n >= NN) return;
    int beg = g_coff[n];
    int deg = g_ideg[n];
    float2 a[4];
    #pragma unroll
    for (int j = 0; j < 4; j++) a[j] = make_float2(0.f, 0.f);

    int i = 0;
    for (; i + 3 < deg; i += 4) {
        int s0 = __ldg(g_esrc + beg + i);
        int s1 = __ldg(g_esrc + beg + i + 1);
        int s2 = __ldg(g_esrc + beg + i + 2);
        int s3 = __ldg(g_esrc + beg + i + 3);
        uint4 v0 = __ldg((const uint4*)(g_z1 + (size_t)s0 * (NB * HIDD)) + lane);
        uint4 v1 = __ldg((const uint4*)(g_z1 + (size_t)s1 * (NB * HIDD)) + lane);
        uint4 v2 = __ldg((const uint4*)(g_z1 + (size_t)s2 * (NB * HIDD)) + lane);
        uint4 v3 = __ldg((const uint4*)(g_z1 + (size_t)s3 * (NB * HIDD)) + lane);
        const unsigned* w0 = &v0.x;
        const unsigned* w1 = &v1.x;
        const unsigned* w2 = &v2.x;
        const unsigned* w3 = &v3.x;
        #pragma unroll
        for (int j = 0; j < 4; j++) {
            float2 f0 = __half22float2(*(const __half2*)&w0[j]);
            float2 f1 = __half22float2(*(const __half2*)&w1[j]);
            float2 f2 = __half22float2(*(const __half2*)&w2[j]);
            float2 f3 = __half22float2(*(const __half2*)&w3[j]);
            a[j].x += (f0.x + f1.x) + (f2.x + f3.x);
            a[j].y += (f0.y + f1.y) + (f2.y + f3.y);
        }
    }
    for (; i < deg; i++) {
        int s0 = __ldg(g_esrc + beg + i);
        uint4 v0 = __ldg((const uint4*)(g_z1 + (size_t)s0 * (NB * HIDD)) + lane);
        const unsigned* w0 = &v0.x;
        #pragma unroll
        for (int j = 0; j < 4; j++) {
            float2 f0 = __half22float2(*(const __half2*)&w0[j]);
            a[j].x += f0.x;
            a[j].y += f0.y;
        }
    }
    float* ap = g_agg1 + (size_t)n * (NB * HIDD) + lane * 8;
    *(float4*)(ap)     = make_float4(a[0].x, a[0].y, a[1].x, a[1].y);
    *(float4*)(ap + 4) = make_float4(a[2].x, a[2].y, a[3].x, a[3].y);
}

// ---------------- GEMM 2: z2[q] = half( snorm * (relu(agg1*dnorm + b1) @ W2) ) ----------------
__global__ void __launch_bounds__(256) k_gemm2(const float* __restrict__ W2,
                                               const float* __restrict__ b1) {
    __shared__ float sA[HIDD][128];
    __shared__ float sB[HIDD * OUTD];
    int tid = threadIdx.x;
    int lane = tid & 31;
    int cgrp = tid >> 5;
    int c0 = cgrp * 4;
    int row0 = blockIdx.x * 128;

    #pragma unroll
    for (int i = tid; i < HIDD * OUTD; i += 256) sB[i] = __ldg(W2 + i);
    #pragma unroll
    for (int it = 0; it < 8; it++) {
        int idx = tid + it * 256;
        int r_l = idx >> 4;
        int kq  = idx & 15;
        int row = row0 + r_l;
        float4 v = make_float4(0.f, 0.f, 0.f, 0.f);
        if (row < NROWS) {
            float dn = g_dnorm[row >> 2];
            float4 a = *(const float4*)(g_agg1 + (size_t)row * HIDD + kq * 4);
            const float4 bb = __ldg((const float4*)(b1 + kq * 4));
            v.x = fmaxf(a.x * dn + bb.x, 0.f);
            v.y = fmaxf(a.y * dn + bb.y, 0.f);
            v.z = fmaxf(a.z * dn + bb.z, 0.f);
            v.w = fmaxf(a.w * dn + bb.w, 0.f);
        }
        int col = r_l ^ kq;
        sA[kq * 4 + 0][col] = v.x;
        sA[kq * 4 + 1][col] = v.y;
        sA[kq * 4 + 2][col] = v.z;
        sA[kq * 4 + 3][col] = v.w;
    }
    __syncthreads();

    u64 acc[4][2];
    #pragma unroll
    for (int r = 0; r < 4; r++) { acc[r][0] = 0ull; acc[r][1] = 0ull; }

    #pragma unroll 4
    for (int k = 0; k < HIDD; k++) {
        int s = (k >> 2) & 15;
        u64 ap[4];
        #pragma unroll
        for (int r = 0; r < 4; r++) {
            float a = sA[k][(lane + 32 * r) ^ s];
            ap[r] = pack2(a, a);
        }
        ulonglong2 b01 = *(const ulonglong2*)&sB[k * OUTD + c0];
        #pragma unroll
        for (int r = 0; r < 4; r++) {
            ffma2(acc[r][0], ap[r], b01.x);
            ffma2(acc[r][1], ap[r], b01.y);
        }
    }

    #pragma unroll
    for (int r = 0; r < 4; r++) {
        int row = row0 + lane + 32 * r;
        if (row >= NROWS) continue;
        float sc = g_snorm[row >> 2];
        float2 p0 = unpack2(acc[r][0]), p1 = unpack2(acc[r][1]);
        __half2 h0 = __floats2half2_rn(sc * p0.x, sc * p0.y);
        __half2 h1 = __floats2half2_rn(sc * p1.x, sc * p1.y);
        uint2 st;
        st.x = *(unsigned*)&h0; st.y = *(unsigned*)&h1;
        *(uint2*)(g_z2 + (size_t)row * OUTD + c0) = st;   // 8B aligned
    }
}

// ---------------- gather layer 2 + fused epilogue -> out[b][n][f] ----------------
__global__ void __launch_bounds__(256) k_agg2(const float* __restrict__ b2,
                                              float* __restrict__ out) {
    int lane = threadIdx.x & 31;
    int n = blockIdx.x * 8 + (threadIdx.x >> 5);
    if (n >= NN) return;
    int beg = g_coff[n];
    int deg = g_ideg[n];
    float2 a0 = make_float2(0.f, 0.f), a1 = a0;

    int i = 0;
    for (; i + 3 < deg; i += 4) {
        int s0 = __ldg(g_esrc + beg + i);
        int s1 = __ldg(g_esrc + beg + i + 1);
        int s2 = __ldg(g_esrc + beg + i + 2);
        int s3 = __ldg(g_esrc + beg + i + 3);
        uint2 v0 = __ldg((const uint2*)(g_z2 + (size_t)s0 * (NB * OUTD)) + lane);
        uint2 v1 = __ldg((const uint2*)(g_z2 + (size_t)s1 * (NB * OUTD)) + lane);
        uint2 v2 = __ldg((const uint2*)(g_z2 + (size_t)s2 * (NB * OUTD)) + lane);
        uint2 v3 = __ldg((const uint2*)(g_z2 + (size_t)s3 * (NB * OUTD)) + lane);
        float2 f;
        f = __half22float2(*(const __half2*)&v0.x); a0.x += f.x; a0.y += f.y;
        f = __half22float2(*(const __half2*)&v0.y); a1.x += f.x; a1.y += f.y;
        f = __half22float2(*(const __half2*)&v1.x); a0.x += f.x; a0.y += f.y;
        f = __half22float2(*(const __half2*)&v1.y); a1.x += f.x; a1.y += f.y;
        f = __half22float2(*(const __half2*)&v2.x); a0.x += f.x; a0.y += f.y;
        f = __half22float2(*(const __half2*)&v2.y); a1.x += f.x; a1.y += f.y;
        f = __half22float2(*(const __half2*)&v3.x); a0.x += f.x; a0.y += f.y;
        f = __half22float2(*(const __half2*)&v3.y); a1.x += f.x; a1.y += f.y;
    }
    for (; i < deg; i++) {
        int s0 = __ldg(g_esrc + beg + i);
        uint2 v0 = __ldg((const uint2*)(g_z2 + (size_t)s0 * (NB * OUTD)) + lane);
        float2 f;
        f = __half22float2(*(const __half2*)&v0.x); a0.x += f.x; a0.y += f.y;
        f = __half22float2(*(const __half2*)&v0.y); a1.x += f.x; a1.y += f.y;
    }

    float dn = g_dnorm[n];
    int b = lane >> 3, fq = lane & 7;
    float4 bb = __ldg((const float4*)(b2 + fq * 4));
    float4 o = make_float4(a0.x * dn + bb.x, a0.y * dn + bb.y,
                           a1.x * dn + bb.z, a1.y * dn + bb.w);
    *(float4*)(out + ((size_t)b * NN + n) * OUTD + fq * 4) = o;
}

// ---------------- launch ----------------

extern "C" void kernel_launch(void* const* d_in, const int* in_sizes, int n_in,
                              void* d_out, int out_size) {
    const float* h  = (const float*)d_in[0];
    const float* W1 = (const float*)d_in[1];
    const float* b1 = (const float*)d_in[2];
    const float* W2 = (const float*)d_in[3];
    const float* b2 = (const float*)d_in[4];
    const int* src  = (const int*)d_in[5];
    const int* dst  = (const int*)d_in[6];
    float* out = (float*)d_out;

    k_zero_deg<<<(NN + 255) / 256, 256>>>();
    k_deg<<<2048, 256>>>(src, dst);
    k_scan1<<<N_SCAN_BLKS, SCAN_BLK>>>();
    k_scan2<<<1, 128>>>();
    k_scan3<<<(NN + 255) / 256, 256>>>();
    k_fill<<<2048, 256>>>(src, dst);
    k_gemm1<<<(NROWS + 127) / 128, 256>>>(h, W1);
    k_agg1<<<(NN + 7) / 8, 256>>>();
    k_gemm2<<<(NROWS + 127) / 128, 256>>>(W2, b1);
    k_agg2<<<(NN + 7) / 8, 256>>>(b2, out);
}